// round 7
// baseline (speedup 1.0000x reference)
#include <cuda_runtime.h>
#include <cstdint>

#define D        32
#define HID      128
#define GRID_G   64
#define NN       4096
#define BB       8
#define TOTAL    (BB*NN)   // 32768 nodes
#define ROW      80        // floats per node row
#define NT       32        // nodes per CTA
#define XSTR     68        // X smem row stride (floats)

// xi-contribution scratch: C[net][node][j] (includes b1)
__device__ float g_C[2][TOTAL * HID];

// ---- packed f32x2 helpers ----
#define FMA2(d, a, b, c) \
    asm("fma.rn.f32x2 %0, %1, %2, %3;" : "=l"(d) : "l"(a), "l"(b), "l"(c))
#define ADD2(d, a, b) \
    asm("add.rn.f32x2 %0, %1, %2;" : "=l"(d) : "l"(a), "l"(b))
#define PACK2(d, lo, hi) \
    asm("mov.b64 %0, {%1, %2};" : "=l"(d) : "f"(lo), "f"(hi))
#define UNPACK2(lo, hi, s) \
    asm("mov.b64 {%0, %1}, %2;" : "=f"(lo), "=f"(hi) : "l"(s))

__device__ __forceinline__ float tanh_fast(float x) {
    float e = __expf(x + x);
    return 1.0f - __fdividef(2.0f, e + 1.0f);
}

// ---------------------------------------------------------------------------
// Precompute C[which][n][j] = b1[j] + sum_k xi[n][k] * W1[64+k][j]
// ---------------------------------------------------------------------------
__global__ void __launch_bounds__(128)
precompute_C_kernel(const float* __restrict__ x,
                    const float* __restrict__ W1,
                    const float* __restrict__ b1,
                    int which)
{
    __shared__ float W1cs[16 * HID];  // [j][k]
    __shared__ float b1s[HID];
    const int tid = threadIdx.x;
    for (int idx = tid; idx < 16 * HID; idx += 128) {
        int k = idx >> 7, j = idx & 127;
        W1cs[j * 16 + k] = W1[(64 + k) * HID + j];
    }
    if (tid < HID) b1s[tid] = b1[tid];
    __syncthreads();

    const int n = blockIdx.x * 128 + tid;
    const float4* xiv = (const float4*)(x + (size_t)n * ROW + 2 * D);
    unsigned long long xp8[8];
    #pragma unroll
    for (int i = 0; i < 4; i++) {
        float4 v = xiv[i];
        PACK2(xp8[2 * i],     v.x, v.y);
        PACK2(xp8[2 * i + 1], v.z, v.w);
    }
    float* Crow = g_C[which] + (size_t)n * HID;
    for (int jb = 0; jb < 32; jb++) {
        float s[4];
        #pragma unroll
        for (int jj = 0; jj < 4; jj++) {
            int j = jb * 4 + jj;
            const ulonglong2* wp = (const ulonglong2*)(W1cs + j * 16);
            unsigned long long a0 = 0ull, a1 = 0ull;
            #pragma unroll
            for (int u = 0; u < 4; u++) {
                ulonglong2 w = wp[u];
                FMA2(a0, xp8[2 * u],     w.x, a0);
                FMA2(a1, xp8[2 * u + 1], w.y, a1);
            }
            ADD2(a0, a0, a1);
            float lo, hi;
            UNPACK2(lo, hi, a0);
            s[jj] = lo + hi + b1s[j];
        }
        *(float4*)(Crow + jb * 4) = make_float4(s[0], s[1], s[2], s[3]);
    }
}

// ---------------------------------------------------------------------------
// Half-update, weight-stationary, PDL-overlapped prologue:
//   prologue (state-independent): W1 column -> regs, C tile -> smem.
//   griddepcontrol.wait, then gather / GEMM1+tanh / GEMM2 / writeback.
// ---------------------------------------------------------------------------
__global__ void __launch_bounds__(128, 4)
half_step_kernel(float* __restrict__ state,
                 const float* __restrict__ tfin,
                 const float* __restrict__ W1,   // (80,128) k-major
                 const float* __restrict__ W2,   // (128,32) j-major
                 const float* __restrict__ b2,   // (32)
                 int which,
                 int zoff, int toff,
                 float tstart, float dtmax)
{
    __shared__ float Xs[NT * XSTR];      // 2176 floats
    __shared__ float Hs[NT * HID];       // 4096 floats
    __shared__ float Ps[2 * NT * D];     // 2048 floats
    __shared__ float Cs[NT * HID];       // 4096 floats (C tile)

    const int tid = threadIdx.x;
    const int node_base = blockIdx.x * NT;

    // Let the successor kernel start its (state-independent) prologue.
    asm volatile("griddepcontrol.launch_dependents;");

    // ---- prologue: state-independent loads ----
    const int j = tid;
    unsigned long long w1p[32];
    #pragma unroll
    for (int i = 0; i < 32; i++)
        PACK2(w1p[i], W1[(2 * i) * HID + j], W1[(2 * i + 1) * HID + j]);

    {   // stage C tile: 32 nodes x 128 j, coalesced float4
        const float4* Cbase =
            (const float4*)(g_C[which] + (size_t)node_base * HID);
        float4* Cdst = (float4*)Cs;
        #pragma unroll
        for (int i = 0; i < (NT * HID / 4) / 128; i++)
            Cdst[i * 128 + tid] = Cbase[i * 128 + tid];
    }

    // Wait for predecessor's state writes before touching `state`.
    asm volatile("griddepcontrol.wait;");

    // ---- Phase G: gather ----
    {
        const int n    = tid >> 2;       // 0..31
        const int part = tid & 3;
        const int node = node_base + n;
        const int nn_  = node & (NN - 1);
        const int r = nn_ >> 6, c = nn_ & (GRID_G - 1);
        const float* rowbase = state + (size_t)(node - nn_) * ROW; // batch base

        if (part < 2) {
            const float4* src = (const float4*)
                (state + (size_t)node * ROW + zoff + part * 16);
            float4* dst = (float4*)(Xs + n * XSTR + part * 16);
            #pragma unroll
            for (int i = 0; i < 4; i++) dst[i] = src[i];
        } else {
            const int nu = (((r + GRID_G - 1) & (GRID_G - 1)) << 6) | c;
            const int nd = (((r + 1) & (GRID_G - 1)) << 6) | c;
            const int nl = (r << 6) | ((c + GRID_G - 1) & (GRID_G - 1));
            const int nr = (r << 6) | ((c + 1) & (GRID_G - 1));
            const int koff = (part - 2) * 16;
            const float4* pu = (const float4*)(rowbase + (size_t)nu * ROW + zoff + koff);
            const float4* pd = (const float4*)(rowbase + (size_t)nd * ROW + zoff + koff);
            const float4* pl = (const float4*)(rowbase + (size_t)nl * ROW + zoff + koff);
            const float4* pr = (const float4*)(rowbase + (size_t)nr * ROW + zoff + koff);
            float4* dst = (float4*)(Xs + n * XSTR + 32 + koff);
            #pragma unroll
            for (int i = 0; i < 4; i++) {
                float4 a = pu[i], b = pd[i], e = pl[i], f = pr[i];
                float4 m;
                m.x = 0.25f * (a.x + b.x + e.x + f.x);
                m.y = 0.25f * (a.y + b.y + e.y + f.y);
                m.z = 0.25f * (a.z + b.z + e.z + f.z);
                m.w = 0.25f * (a.w + b.w + e.w + f.w);
                dst[i] = m;
            }
        }
    }
    __syncthreads();

    // ---- Phase A: GEMM1 + tanh, weights in regs, x broadcast from smem ----
    {
        #pragma unroll 2
        for (int n = 0; n < NT; n++) {
            float cv = Cs[n * HID + j];
            const ulonglong2* xr = (const ulonglong2*)(Xs + n * XSTR);
            unsigned long long a0 = 0ull, a1 = 0ull, a2 = 0ull, a3 = 0ull;
            #pragma unroll
            for (int i = 0; i < 16; i += 2) {
                ulonglong2 u = xr[i];
                ulonglong2 v = xr[i + 1];
                FMA2(a0, u.x, w1p[2 * i],     a0);
                FMA2(a1, u.y, w1p[2 * i + 1], a1);
                FMA2(a2, v.x, w1p[2 * i + 2], a2);
                FMA2(a3, v.y, w1p[2 * i + 3], a3);
            }
            ADD2(a0, a0, a1);
            ADD2(a2, a2, a3);
            ADD2(a0, a0, a2);
            float lo, hi;
            UNPACK2(lo, hi, a0);
            Hs[n * HID + j] = tanh_fast(lo + hi + cv);
        }
    }
    __syncthreads();

    // ---- Phase B: GEMM2, W2 quarter in regs, strip rotation ----
    {
        const int dlane = tid & 31;
        const int w     = tid >> 5;      // j-quarter
        const int pb    = w >> 1;        // partial buffer

        unsigned long long w2p[16];
        #pragma unroll
        for (int i = 0; i < 16; i++) {
            int jj = w * 32 + 2 * i;
            PACK2(w2p[i], W2[jj * D + dlane], W2[(jj + 1) * D + dlane]);
        }

        for (int s = 0; s < 2; s++) {
            const int st = (w + s) & 1;
            const int n0 = st * 16;
            #pragma unroll 2
            for (int n = n0; n < n0 + 16; n++) {
                const ulonglong2* hr =
                    (const ulonglong2*)(Hs + n * HID + w * 32);
                unsigned long long a0 = 0ull, a1 = 0ull;
                #pragma unroll
                for (int i = 0; i < 8; i += 2) {
                    ulonglong2 u = hr[i];
                    ulonglong2 v = hr[i + 1];
                    FMA2(a0, u.x, w2p[2 * i],     a0);
                    FMA2(a1, u.y, w2p[2 * i + 1], a1);
                    FMA2(a0, v.x, w2p[2 * i + 2], a0);
                    FMA2(a1, v.y, w2p[2 * i + 3], a1);
                }
                ADD2(a0, a0, a1);
                float lo, hi;
                UNPACK2(lo, hi, a0);
                float val = lo + hi;
                float* pp = Ps + pb * (NT * D) + n * D + dlane;
                if (s == 0) *pp = val;
                else        *pp += val;
            }
            __syncthreads();
        }
    }

    // ---- Final: z += dt * (P0 + P1 + b2) ----
    {
        const int bcta = node_base >> 12;
        float tfv = __ldg(tfin + bcta);
        float dtv = fminf(fmaxf(tfv - tstart, 0.0f), dtmax);
        #pragma unroll
        for (int rix = 0; rix < 8; rix++) {
            int idx = rix * 128 + tid;
            int n = idx >> 5, dd = idx & 31;
            float val = Ps[n * D + dd] + Ps[NT * D + n * D + dd]
                      + __ldg(b2 + dd);
            float* gp = state + (size_t)(node_base + n) * ROW + toff + dd;
            *gp += dtv * val;
        }
    }
}

static void launch_half_step(float* state, const float* tf,
                             const float* W1, const float* W2,
                             const float* b2, int which,
                             int zoff, int toff,
                             float tstart, float dtmax)
{
    cudaLaunchConfig_t cfg = {};
    cfg.gridDim  = dim3(TOTAL / NT, 1, 1);   // 1024
    cfg.blockDim = dim3(128, 1, 1);
    cfg.dynamicSmemBytes = 0;
    cfg.stream = 0;
    cudaLaunchAttribute attr[1];
    attr[0].id = cudaLaunchAttributeProgrammaticStreamSerialization;
    attr[0].val.programmaticStreamSerializationAllowed = 1;
    cfg.attrs = attr;
    cfg.numAttrs = 1;
    cudaLaunchKernelEx(&cfg, half_step_kernel,
                       state, (const float*)tf, W1, W2, b2,
                       which, zoff, toff, tstart, dtmax);
}

extern "C" void kernel_launch(void* const* d_in, const int* in_sizes, int n_in,
                              void* d_out, int out_size)
{
    const float* x    = (const float*)d_in[0];
    const float* tf   = (const float*)d_in[1];
    const float* W1q  = (const float*)d_in[2];
    const float* b1q  = (const float*)d_in[3];
    const float* W2q  = (const float*)d_in[4];
    const float* b2q  = (const float*)d_in[5];
    const float* W1p  = (const float*)d_in[6];
    const float* b1p  = (const float*)d_in[7];
    const float* W2p  = (const float*)d_in[8];
    const float* b2p  = (const float*)d_in[9];
    float* state = (float*)d_out;

    cudaMemcpyAsync(state, x, (size_t)out_size * sizeof(float),
                    cudaMemcpyDeviceToDevice);

    precompute_C_kernel<<<TOTAL / 128, 128>>>(x, W1q, b1q, 0);
    precompute_C_kernel<<<TOTAL / 128, 128>>>(x, W1p, b1p, 1);

    const float DT = 0.25f;

    for (int k = 0; k < 18; k++) {
        float tsq = (k == 0) ? 0.0f : (0.125f + (k - 1) * DT);
        float dmq = (k == 0) ? 0.125f : DT;
        launch_half_step(state, tf, W1q, W2q, b2q, /*which=*/0,
                         /*zoff=*/D, /*toff=*/0, tsq, dmq);

        float tsp = k * DT;
        launch_half_step(state, tf, W1p, W2p, b2p, /*which=*/1,
                         /*zoff=*/0, /*toff=*/D, tsp, DT);
    }
    (void)in_sizes; (void)n_in;
}